// round 7
// baseline (speedup 1.0000x reference)
#include <cuda_runtime.h>
#include <cuda_bf16.h>
#include <cstdint>

#define B_  2
#define N_  2048
#define D_  1024
#define H_  16
#define HD_ 64
#define S_  2048
#define BH_ (B_*H_)

// ---------------- scratch ----------------------------------------------------
static __device__ float g_rowsum[(size_t)BH_*N_];

// split-bf16 projection operands
static __device__ __nv_bfloat16 g_xh[(size_t)4096*1024];
static __device__ __nv_bfloat16 g_xl[(size_t)4096*1024];
static __device__ __nv_bfloat16 g_wih[(size_t)3072*1024];
static __device__ __nv_bfloat16 g_wil[(size_t)3072*1024];
static __device__ __nv_bfloat16 g_aoh[(size_t)4096*1024];
static __device__ __nv_bfloat16 g_aol[(size_t)4096*1024];
static __device__ __nv_bfloat16 g_woh[(size_t)1024*1024];
static __device__ __nv_bfloat16 g_wol[(size_t)1024*1024];

// split-bf16 attention operands (written by qkv epilogue)
static __device__ __nv_bfloat16 g_Qh[(size_t)BH_*N_*HD_];   // [bh,n,hd]
static __device__ __nv_bfloat16 g_Ql[(size_t)BH_*N_*HD_];
static __device__ __nv_bfloat16 g_Kh[(size_t)BH_*N_*HD_];
static __device__ __nv_bfloat16 g_Kl[(size_t)BH_*N_*HD_];
static __device__ __nv_bfloat16 g_Vth[(size_t)BH_*HD_*N_];  // [bh,hd,n] transposed
static __device__ __nv_bfloat16 g_Vtl[(size_t)BH_*HD_*N_];

// ---------------- helpers ----------------------------------------------------
__device__ __forceinline__ uint32_t smem_u32(const void* p) {
    uint32_t a;
    asm("{ .reg .u64 t; cvta.to.shared.u64 t, %1; cvt.u32.u64 %0, t; }"
        : "=r"(a) : "l"(p));
    return a;
}
__device__ __forceinline__ void cp16(uint32_t dst, const void* src) {
    asm volatile("cp.async.cg.shared.global [%0], [%1], 16;" :: "r"(dst), "l"(src));
}
#define CP_COMMIT asm volatile("cp.async.commit_group;" ::: "memory")
#define CP_WAIT0  asm volatile("cp.async.wait_group 0;" ::: "memory")
#define CP_WAIT1  asm volatile("cp.async.wait_group 1;" ::: "memory")

__device__ __forceinline__ void ldsm4(uint32_t& r0, uint32_t& r1, uint32_t& r2,
                                      uint32_t& r3, uint32_t addr) {
    asm volatile("ldmatrix.sync.aligned.m8n8.x4.shared.b16 {%0,%1,%2,%3}, [%4];"
                 : "=r"(r0), "=r"(r1), "=r"(r2), "=r"(r3) : "r"(addr));
}
__device__ __forceinline__ void mma16816(float* c, const uint32_t* a,
                                         const uint32_t* b) {
    asm volatile(
        "mma.sync.aligned.m16n8k16.row.col.f32.bf16.bf16.f32 "
        "{%0,%1,%2,%3}, {%4,%5,%6,%7}, {%8,%9}, {%0,%1,%2,%3};"
        : "+f"(c[0]), "+f"(c[1]), "+f"(c[2]), "+f"(c[3])
        : "r"(a[0]), "r"(a[1]), "r"(a[2]), "r"(a[3]), "r"(b[0]), "r"(b[1]));
}
__device__ __forceinline__ uint32_t pkbf(float lo, float hi) {
    uint32_t d;
    asm("cvt.rn.bf16x2.f32 %0, %1, %2;" : "=r"(d) : "f"(hi), "f"(lo));
    return d;
}

// =============================================================================
// fp32 -> bf16 hi/lo split, 3 tensors in one launch (segmented by blockIdx)
// =============================================================================
__global__ void __launch_bounds__(256) cvt3_kernel(
        const float* __restrict__ x0, __nv_bfloat16* __restrict__ h0p,
        __nv_bfloat16* __restrict__ l0p,
        const float* __restrict__ x1, __nv_bfloat16* __restrict__ h1p,
        __nv_bfloat16* __restrict__ l1p,
        const float* __restrict__ x2, __nv_bfloat16* __restrict__ h2p,
        __nv_bfloat16* __restrict__ l2p) {
    int blk = blockIdx.x;
    const float* x; __nv_bfloat16 *hi, *lo; int i;
    if (blk < 4096)      { x = x0; hi = h0p; lo = l0p; i = blk * 256 + threadIdx.x; }
    else if (blk < 7168) { x = x1; hi = h1p; lo = l1p; i = (blk - 4096) * 256 + threadIdx.x; }
    else                 { x = x2; hi = h2p; lo = l2p; i = (blk - 7168) * 256 + threadIdx.x; }
    float4 v = ((const float4*)x)[i];
    __nv_bfloat16 a0 = __float2bfloat16(v.x), a1 = __float2bfloat16(v.y);
    __nv_bfloat16 a2 = __float2bfloat16(v.z), a3 = __float2bfloat16(v.w);
    ((__nv_bfloat162*)hi)[2 * i] = __nv_bfloat162(a0, a1);
    ((__nv_bfloat162*)hi)[2 * i + 1] = __nv_bfloat162(a2, a3);
    ((__nv_bfloat162*)lo)[2 * i] = __nv_bfloat162(
        __float2bfloat16(v.x - __bfloat162float(a0)),
        __float2bfloat16(v.y - __bfloat162float(a1)));
    ((__nv_bfloat162*)lo)[2 * i + 1] = __nv_bfloat162(
        __float2bfloat16(v.z - __bfloat162float(a2)),
        __float2bfloat16(v.w - __bfloat162float(a3)));
}

// =============================================================================
// Split-bf16 GEMM via mma.sync (unchanged — proven)
// =============================================================================
#define SSTR  40
#define ARRB  (128*SSTR*2)
#define STAGE (4*ARRB)
#define GEMM_SMEM (2*STAGE)

__device__ __forceinline__ void split_st2(__nv_bfloat16* dh, __nv_bfloat16* dl,
                                          size_t idx, float2 v) {
    __nv_bfloat16 h0 = __float2bfloat16(v.x), h1 = __float2bfloat16(v.y);
    *(__nv_bfloat162*)(dh + idx) = __nv_bfloat162(h0, h1);
    *(__nv_bfloat162*)(dl + idx) = __nv_bfloat162(
        __float2bfloat16(v.x - __bfloat162float(h0)),
        __float2bfloat16(v.y - __bfloat162float(h1)));
}
__device__ __forceinline__ void split_st1(__nv_bfloat16* dh, __nv_bfloat16* dl,
                                          size_t idx, float v) {
    __nv_bfloat16 h = __float2bfloat16(v);
    dh[idx] = h;
    dl[idx] = __float2bfloat16(v - __bfloat162float(h));
}

template<bool QKV>
__global__ void __launch_bounds__(256) mma_gemm(
        const __nv_bfloat16* __restrict__ Ah_g, const __nv_bfloat16* __restrict__ Al_g,
        const __nv_bfloat16* __restrict__ Bh_g, const __nv_bfloat16* __restrict__ Bl_g,
        const float* __restrict__ bias, float* __restrict__ outp) {
    extern __shared__ char smem[];
    uint32_t sb = smem_u32(smem);
    int tid = threadIdx.x, lane = tid & 31, wid = tid >> 5;
    int m0 = blockIdx.y << 7, n0 = blockIdx.x << 7;
    int wm = wid >> 1, wn = wid & 1;

    const __nv_bfloat16* base[4] = {
        Ah_g + (size_t)m0 * 1024, Al_g + (size_t)m0 * 1024,
        Bh_g + (size_t)n0 * 1024, Bl_g + (size_t)n0 * 1024 };

    float c[2][8][4];
#pragma unroll
    for (int mt = 0; mt < 2; mt++)
#pragma unroll
        for (int nt = 0; nt < 8; nt++)
#pragma unroll
            for (int q = 0; q < 4; q++) c[mt][nt][q] = 0.f;

    int r_ld = tid >> 2, c_ld = (tid & 3) << 3;

    {
#pragma unroll
        for (int arr = 0; arr < 4; arr++)
#pragma unroll
            for (int j = 0; j < 2; j++) {
                int r = r_ld + j * 64;
                cp16(sb + arr * ARRB + (uint32_t)(r * SSTR + c_ld) * 2,
                     base[arr] + (size_t)r * 1024 + c_ld);
            }
        CP_COMMIT;
    }

#pragma unroll 1
    for (int t = 0; t < 32; t++) {
        if (t + 1 < 32) {
            int s = (t + 1) & 1, k0 = (t + 1) << 5;
#pragma unroll
            for (int arr = 0; arr < 4; arr++)
#pragma unroll
                for (int j = 0; j < 2; j++) {
                    int r = r_ld + j * 64;
                    cp16(sb + (uint32_t)s * STAGE + arr * ARRB +
                             (uint32_t)(r * SSTR + c_ld) * 2,
                         base[arr] + (size_t)r * 1024 + k0 + c_ld);
                }
            CP_COMMIT;
            CP_WAIT1;
        } else {
            CP_WAIT0;
        }
        __syncthreads();

        uint32_t st = sb + (uint32_t)(t & 1) * STAGE;
#pragma unroll
        for (int kk = 0; kk < 2; kk++) {
            uint32_t bh[8][2], bl[8][2];
#pragma unroll
            for (int ng = 0; ng < 4; ng++) {
                int brow = wn * 64 + ng * 16 + (lane & 7) + ((lane & 16) >> 1);
                int bcol = kk * 16 + ((lane >> 3) & 1) * 8;
                uint32_t ba = st + 2 * ARRB + (uint32_t)(brow * SSTR + bcol) * 2;
                ldsm4(bh[2 * ng][0], bh[2 * ng][1], bh[2 * ng + 1][0],
                      bh[2 * ng + 1][1], ba);
                ldsm4(bl[2 * ng][0], bl[2 * ng][1], bl[2 * ng + 1][0],
                      bl[2 * ng + 1][1], ba + ARRB);
            }
#pragma unroll
            for (int mt = 0; mt < 2; mt++) {
                int arow = wm * 32 + mt * 16 + (lane & 15);
                int acol = kk * 16 + (lane >> 4) * 8;
                uint32_t aa = st + (uint32_t)(arow * SSTR + acol) * 2;
                uint32_t ah[4], al[4];
                ldsm4(ah[0], ah[1], ah[2], ah[3], aa);
                ldsm4(al[0], al[1], al[2], al[3], aa + ARRB);
#pragma unroll
                for (int nt = 0; nt < 8; nt++) {
                    mma16816(c[mt][nt], ah, bh[nt]);
                    mma16816(c[mt][nt], ah, bl[nt]);
                    mma16816(c[mt][nt], al, bh[nt]);
                }
            }
        }
        __syncthreads();
    }

    // ---------------- epilogue ----------------
#pragma unroll
    for (int mt = 0; mt < 2; mt++) {
        int m = m0 + wm * 32 + mt * 16 + (lane >> 2);
#pragma unroll
        for (int nt = 0; nt < 8; nt++) {
            int n = n0 + wn * 64 + nt * 8 + ((lane & 3) << 1);
            float b0 = bias[n], b1 = bias[n + 1];
            float2 v0 = make_float2(c[mt][nt][0] + b0, c[mt][nt][1] + b1);
            float2 v1 = make_float2(c[mt][nt][2] + b0, c[mt][nt][3] + b1);
            if (QKV) {
                int sect = n >> 10;
                int h = (n & 1023) >> 6, hd = n & 63;
                int bb = m >> 11, row = m & 2047;
                int bh_i = bb * H_ + h;
                if (sect < 2) {
                    __nv_bfloat16* dh = sect == 0 ? g_Qh : g_Kh;
                    __nv_bfloat16* dl = sect == 0 ? g_Ql : g_Kl;
                    size_t p = ((size_t)bh_i * N_ + row) * HD_ + hd;
                    split_st2(dh, dl, p, v0);
                    split_st2(dh, dl, p + 8 * HD_, v1);
                } else {
                    size_t pb = ((size_t)bh_i * HD_ + hd) * N_ + row;
                    split_st1(g_Vth, g_Vtl, pb, v0.x);
                    split_st1(g_Vth, g_Vtl, pb + N_, v0.y);
                    split_st1(g_Vth, g_Vtl, pb + 8, v1.x);
                    split_st1(g_Vth, g_Vtl, pb + N_ + 8, v1.y);
                }
            } else {
                float* p = outp + (size_t)m * 1024 + n;
                *(float2*)p = v0;
                *(float2*)(p + 8 * 1024) = v1;
            }
        }
    }
}

// =============================================================================
// HMMA split-bf16 fused attention, 4-stage KV ring + deferred AV(t-1):
// iter t issues S(t) MMAs, then AV(t-1) MMAs (independent — fill tensor pipe
// while S results are in flight), then exp(t) overlapping the AV drain.
// =============================================================================
#define AT_STR 72
#define AQH 0
#define AQL (128*AT_STR)
#define AKV (2*128*AT_STR)
#define KVSTG (4*64*AT_STR)
#define ABF_END (AKV + 4*KVSTG)
#define ATTN_SMEM (ABF_END*2 + 2048*4)      // 192512 B

__global__ void __launch_bounds__(256, 1) attn_kernel(float* __restrict__ attn,
                                                      const float* __restrict__ rpe,
                                                      int write_attn) {
    extern __shared__ char smc[];
    uint32_t sb = smem_u32(smc);
    float* rc = (float*)(smc + ABF_END * 2);

    int qt = blockIdx.x, h = blockIdx.y, b = blockIdx.z;
    int bh_i = b * H_ + h;
    int tid = threadIdx.x, lane = tid & 31, wm = tid >> 5;
    int q0 = qt << 7;

    for (int i = tid; i < S_; i += 256) rc[i] = rpe[(size_t)i * H_ + h];

    const __nv_bfloat16* qhg = g_Qh + ((size_t)bh_i * N_ + q0) * HD_;
    const __nv_bfloat16* qlg = g_Ql + ((size_t)bh_i * N_ + q0) * HD_;
    const __nv_bfloat16* khg = g_Kh + (size_t)bh_i * N_ * HD_;
    const __nv_bfloat16* klg = g_Kl + (size_t)bh_i * N_ * HD_;
    const __nv_bfloat16* vhg = g_Vth + (size_t)bh_i * HD_ * N_;
    const __nv_bfloat16* vlg = g_Vtl + (size_t)bh_i * HD_ * N_;

#pragma unroll
    for (int j = 0; j < 4; j++) {
        int u = tid + j * 256;
        int r = u >> 3, ch = (u & 7) << 3;
        cp16(sb + (uint32_t)(AQH + r * AT_STR + ch) * 2, qhg + (size_t)r * HD_ + ch);
        cp16(sb + (uint32_t)(AQL + r * AT_STR + ch) * 2, qlg + (size_t)r * HD_ + ch);
    }
    CP_COMMIT;

    int r_ld = tid >> 3, c_ld = (tid & 7) << 3;
    auto issue_kv = [&](int t) {
        int k0g = t * 64;
        uint32_t stg = sb + (uint32_t)(AKV + (t & 3) * KVSTG) * 2;
#pragma unroll
        for (int j = 0; j < 2; j++) {
            int r = r_ld + j * 32, ch = c_ld;
            cp16(stg + (uint32_t)(0 * 4608 + r * AT_STR + ch) * 2,
                 khg + (size_t)(k0g + r) * HD_ + ch);
            cp16(stg + (uint32_t)(1 * 4608 + r * AT_STR + ch) * 2,
                 klg + (size_t)(k0g + r) * HD_ + ch);
            cp16(stg + (uint32_t)(2 * 4608 + r * AT_STR + ch) * 2,
                 vhg + (size_t)r * N_ + k0g + ch);
            cp16(stg + (uint32_t)(3 * 4608 + r * AT_STR + ch) * 2,
                 vlg + (size_t)r * N_ + k0g + ch);
        }
        CP_COMMIT;
    };
    issue_kv(0);
    issue_kv(1);

    float co[8][4];
#pragma unroll
    for (int nh = 0; nh < 8; nh++)
#pragma unroll
        for (int q = 0; q < 4; q++) co[nh][q] = 0.f;
    float rs0 = 0.f, rs1 = 0.f;

    uint32_t peh[4][4], pel[4][4];       // previous tile's e-fragments

    int row_q = q0 + wm * 16 + (lane >> 2);
    const float scale = 0.125f;

#pragma unroll 1
    for (int t = 0; t < N_ / 64; t++) {
        if (t < 31) { CP_WAIT1; } else { CP_WAIT0; }
        __syncthreads();

        int k0g = t * 64;
        uint32_t kb = sb + (uint32_t)(AKV + (t & 3) * KVSTG) * 2;

        // ---- S = Q.K^T (stage t) ----
        float s[8][4];
#pragma unroll
        for (int nt = 0; nt < 8; nt++)
#pragma unroll
            for (int q = 0; q < 4; q++) s[nt][q] = 0.f;
#pragma unroll
        for (int ks = 0; ks < 4; ks++) {
            int arow = wm * 16 + (lane & 15);
            int acol = ks * 16 + (lane >> 4) * 8;
            uint32_t aa = sb + (uint32_t)(AQH + arow * AT_STR + acol) * 2;
            uint32_t ah[4], al[4];
            ldsm4(ah[0], ah[1], ah[2], ah[3], aa);
            ldsm4(al[0], al[1], al[2], al[3], aa + AQL * 2);
            uint32_t bh[8][2], bl[8][2];
#pragma unroll
            for (int ng = 0; ng < 4; ng++) {
                int brow = ng * 16 + (lane & 7) + ((lane & 16) >> 1);
                int bcol = ks * 16 + ((lane >> 3) & 1) * 8;
                uint32_t ba = kb + (uint32_t)(brow * AT_STR + bcol) * 2;
                ldsm4(bh[2 * ng][0], bh[2 * ng][1], bh[2 * ng + 1][0],
                      bh[2 * ng + 1][1], ba);
                ldsm4(bl[2 * ng][0], bl[2 * ng][1], bl[2 * ng + 1][0],
                      bl[2 * ng + 1][1], ba + 4608 * 2);
            }
#pragma unroll
            for (int nt = 0; nt < 8; nt++) {
                mma16816(s[nt], ah, bh[nt]);
                mma16816(s[nt], ah, bl[nt]);
                mma16816(s[nt], al, bh[nt]);
            }
        }

        // ---- deferred AV(t-1): independent of pending S results ----
        if (t > 0) {
            uint32_t vb0 = sb + (uint32_t)(AKV + ((t - 1) & 3) * KVSTG) * 2
                         + 2 * 4608 * 2;
#pragma unroll
            for (int ks = 0; ks < 4; ks++) {
                uint32_t vbh[8][2], vbl[8][2];
#pragma unroll
                for (int ng = 0; ng < 4; ng++) {
                    int brow = ng * 16 + (lane & 7) + ((lane & 16) >> 1);
                    int bcol = ks * 16 + ((lane >> 3) & 1) * 8;
                    uint32_t ba = vb0 + (uint32_t)(brow * AT_STR + bcol) * 2;
                    ldsm4(vbh[2 * ng][0], vbh[2 * ng][1], vbh[2 * ng + 1][0],
                          vbh[2 * ng + 1][1], ba);
                    ldsm4(vbl[2 * ng][0], vbl[2 * ng][1], vbl[2 * ng + 1][0],
                          vbl[2 * ng + 1][1], ba + 4608 * 2);
                }
#pragma unroll
                for (int nh = 0; nh < 8; nh++) {
                    mma16816(co[nh], peh[ks], vbh[nh]);
                    mma16816(co[nh], peh[ks], vbl[nh]);
                    mma16816(co[nh], pel[ks], vbh[nh]);
                }
            }
        }

        // ---- bias + exp + rowsum + attn store (overlaps AV drain) ----
#pragma unroll
        for (int nt = 0; nt < 8; nt++) {
            int col = k0g + nt * 8 + ((lane & 3) << 1);
            int d0 = row_q - col;     if (d0 < 0) d0 = -d0;
            int d1 = row_q - col - 1; if (d1 < 0) d1 = -d1;
            int d2 = row_q + 8 - col;     if (d2 < 0) d2 = -d2;
            int d3 = row_q + 8 - col - 1; if (d3 < 0) d3 = -d3;
            float e0 = __expf(fmaf(s[nt][0], scale, rc[d0]));
            float e1 = __expf(fmaf(s[nt][1], scale, rc[d1]));
            float e2 = __expf(fmaf(s[nt][2], scale, rc[d2]));
            float e3 = __expf(fmaf(s[nt][3], scale, rc[d3]));
            s[nt][0] = e0; s[nt][1] = e1; s[nt][2] = e2; s[nt][3] = e3;
            rs0 += e0 + e1;
            rs1 += e2 + e3;
            if (write_attn) {
                float* ap = attn + ((size_t)bh_i * N_ + row_q) * N_ + col;
                *(float2*)ap = make_float2(e0, e1);
                *(float2*)(ap + 8 * N_) = make_float2(e2, e3);
            }
        }

        // ---- pack e(t) into register fragments for next iteration ----
#pragma unroll
        for (int ks = 0; ks < 4; ks++) {
            float c0 = s[2 * ks][0], c1 = s[2 * ks][1];
            float c2 = s[2 * ks][2], c3 = s[2 * ks][3];
            float c4 = s[2 * ks + 1][0], c5 = s[2 * ks + 1][1];
            float c6 = s[2 * ks + 1][2], c7 = s[2 * ks + 1][3];
            peh[ks][0] = pkbf(c0, c1); peh[ks][1] = pkbf(c2, c3);
            peh[ks][2] = pkbf(c4, c5); peh[ks][3] = pkbf(c6, c7);
            float hh;
            hh = __bfloat162float(__float2bfloat16(c0)); c0 -= hh;
            hh = __bfloat162float(__float2bfloat16(c1)); c1 -= hh;
            hh = __bfloat162float(__float2bfloat16(c2)); c2 -= hh;
            hh = __bfloat162float(__float2bfloat16(c3)); c3 -= hh;
            hh = __bfloat162float(__float2bfloat16(c4)); c4 -= hh;
            hh = __bfloat162float(__float2bfloat16(c5)); c5 -= hh;
            hh = __bfloat162float(__float2bfloat16(c6)); c6 -= hh;
            hh = __bfloat162float(__float2bfloat16(c7)); c7 -= hh;
            pel[ks][0] = pkbf(c0, c1); pel[ks][1] = pkbf(c2, c3);
            pel[ks][2] = pkbf(c4, c5); pel[ks][3] = pkbf(c6, c7);
        }

        if (t + 2 < N_ / 64) issue_kv(t + 2);
    }

    // ---- final AV for the last tile (stage 31 & 3) ----
    {
        uint32_t vb0 = sb + (uint32_t)(AKV + (31 & 3) * KVSTG) * 2 + 2 * 4608 * 2;
#pragma unroll
        for (int ks = 0; ks < 4; ks++) {
            uint32_t vbh[8][2], vbl[8][2];
#pragma unroll
            for (int ng = 0; ng < 4; ng++) {
                int brow = ng * 16 + (lane & 7) + ((lane & 16) >> 1);
                int bcol = ks * 16 + ((lane >> 3) & 1) * 8;
                uint32_t ba = vb0 + (uint32_t)(brow * AT_STR + bcol) * 2;
                ldsm4(vbh[2 * ng][0], vbh[2 * ng][1], vbh[2 * ng + 1][0],
                      vbh[2 * ng + 1][1], ba);
                ldsm4(vbl[2 * ng][0], vbl[2 * ng][1], vbl[2 * ng + 1][0],
                      vbl[2 * ng + 1][1], ba + 4608 * 2);
            }
#pragma unroll
            for (int nh = 0; nh < 8; nh++) {
                mma16816(co[nh], peh[ks], vbh[nh]);
                mma16816(co[nh], peh[ks], vbl[nh]);
                mma16816(co[nh], pel[ks], vbh[nh]);
            }
        }
    }

    // ---- rowsum reduce over quad lanes ----
    rs0 += __shfl_xor_sync(0xffffffffu, rs0, 1);
    rs0 += __shfl_xor_sync(0xffffffffu, rs0, 2);
    rs1 += __shfl_xor_sync(0xffffffffu, rs1, 1);
    rs1 += __shfl_xor_sync(0xffffffffu, rs1, 2);
    if ((lane & 3) == 0) {
        g_rowsum[(size_t)bh_i * N_ + row_q] = rs0;
        g_rowsum[(size_t)bh_i * N_ + row_q + 8] = rs1;
    }

    // ---- normalized output -> split-bf16 aoh/aol ----
    float inv0 = 1.0f / rs0, inv1 = 1.0f / rs1;
#pragma unroll
    for (int nh = 0; nh < 8; nh++) {
        int hd = nh * 8 + ((lane & 3) << 1);
        size_t p = ((size_t)(b * N_ + row_q)) * D_ + h * HD_ + hd;
        split_st2(g_aoh, g_aol, p, make_float2(co[nh][0] * inv0, co[nh][1] * inv0));
        split_st2(g_aoh, g_aol, p + 8 * D_,
                  make_float2(co[nh][2] * inv1, co[nh][3] * inv1));
    }
}

// =============================================================================
__global__ void __launch_bounds__(256) norm_kernel(float* __restrict__ attn) {
    size_t i = (size_t)blockIdx.x * 256 + threadIdx.x;
    const size_t total = (size_t)BH_ * N_ * N_ / 4;
    if (i >= total) return;
    size_t e0 = i << 2;
    int row = (int)(e0 >> 11);
    float inv = 1.0f / g_rowsum[row];
    float4 v = __ldcs((const float4*)attn + i);
    v.x *= inv; v.y *= inv; v.z *= inv; v.w *= inv;
    __stcs((float4*)attn + i, v);
}

// =============================================================================
extern "C" void kernel_launch(void* const* d_in, const int* in_sizes, int n_in,
                              void* d_out, int out_size) {
    const float* query = (const float*)d_in[0];
    const float* w_in  = (const float*)d_in[4];
    const float* b_in  = (const float*)d_in[5];
    const float* w_out = (const float*)d_in[6];
    const float* b_out = (const float*)d_in[7];
    const float* rpe   = (const float*)d_in[8];

    float* out  = (float*)d_out;
    const long long out_elems  = (long long)B_ * N_ * D_;
    const long long attn_elems = (long long)BH_ * N_ * N_;
    int write_attn = ((long long)out_size >= out_elems + attn_elems) ? 1 : 0;
    float* attn = out + out_elems;

    cudaFuncSetAttribute(attn_kernel, cudaFuncAttributeMaxDynamicSharedMemorySize,
                         ATTN_SMEM);
    cudaFuncSetAttribute(mma_gemm<true>, cudaFuncAttributeMaxDynamicSharedMemorySize,
                         GEMM_SMEM);
    cudaFuncSetAttribute(mma_gemm<false>, cudaFuncAttributeMaxDynamicSharedMemorySize,
                         GEMM_SMEM);

    __nv_bfloat16 *xh, *xl, *wih, *wil, *aoh, *aol, *woh, *wol;
    cudaGetSymbolAddress((void**)&xh,  g_xh);
    cudaGetSymbolAddress((void**)&xl,  g_xl);
    cudaGetSymbolAddress((void**)&wih, g_wih);
    cudaGetSymbolAddress((void**)&wil, g_wil);
    cudaGetSymbolAddress((void**)&aoh, g_aoh);
    cudaGetSymbolAddress((void**)&aol, g_aol);
    cudaGetSymbolAddress((void**)&woh, g_woh);
    cudaGetSymbolAddress((void**)&wol, g_wol);

    cvt3_kernel<<<8192, 256>>>(query, xh, xl, w_in, wih, wil, w_out, woh, wol);

    mma_gemm<true><<<dim3(24, 32), 256, GEMM_SMEM>>>(xh, xl, wih, wil, b_in, nullptr);

    attn_kernel<<<dim3(16, 16, 2), 256, ATTN_SMEM>>>(attn, rpe, write_attn);
    if (write_attn) {
        const int total_f4 = (int)((long long)BH_ * N_ * N_ / 4);
        norm_kernel<<<(total_f4 + 255) / 256, 256>>>(attn);
    }

    mma_gemm<false><<<dim3(8, 32), 256, GEMM_SMEM>>>(aoh, aol, woh, wol, b_out, out);
}